// round 17
// baseline (speedup 1.0000x reference)
#include <cuda_runtime.h>
#include <cuda_bf16.h>
#include <cstdint>

// Problem constants
#define NN      500000
#define DIM     256
#define JDIM    64
#define BMAX    512
#define TILE    64
#define XSTR    272                   // floats per xs row (1088B: conflict-free mma B reads)
#define XBUF    (TILE * XSTR)         // floats per buffer
#define GRID    152                   // GB300 SM count; 1 block/SM (smem-limited)

// ---------------- device scratch (static, no allocation) ----------------
__device__ float    g_segsum[BMAX];
__device__ float    g_pooled[BMAX * DIM];
__device__ int      g_is64;

// ---------------- helpers ----------------
__device__ __forceinline__ uint32_t f2tf32(float f) {
    uint32_t u; asm("cvt.rna.tf32.f32 %0, %1;" : "=r"(u) : "f"(f)); return u;
}
__device__ __forceinline__ float tanh_apx(float x) {
    float y; asm("tanh.approx.f32 %0, %1;" : "=f"(y) : "f"(x)); return y;
}
__device__ __forceinline__ void mma_tf32(float (&c)[4],
        uint32_t a0, uint32_t a1, uint32_t a2, uint32_t a3,
        uint32_t b0, uint32_t b1) {
    asm volatile(
        "mma.sync.aligned.m16n8k8.row.col.f32.tf32.tf32.f32 "
        "{%0,%1,%2,%3}, {%4,%5,%6,%7}, {%8,%9}, {%0,%1,%2,%3};\n"
        : "+f"(c[0]), "+f"(c[1]), "+f"(c[2]), "+f"(c[3])
        : "r"(a0), "r"(a1), "r"(a2), "r"(a3), "r"(b0), "r"(b1));
}
__device__ __forceinline__ void cp_async16(uint32_t dst, const void* src) {
    asm volatile("cp.async.cg.shared.global [%0], [%1], 16;" :: "r"(dst), "l"(src));
}
#define CP_COMMIT() asm volatile("cp.async.commit_group;" ::: "memory")
#define CP_WAIT0()  asm volatile("cp.async.wait_group 0;" ::: "memory")

// ---------------- kernel 0: detect batch dtype (int32 vs int64) ----------------
__global__ void detect_kernel(const void* batch) {
    const int* w = (const int*)batch;
    __shared__ int cnt;
    if (threadIdx.x == 0) cnt = 0;
    __syncthreads();
    int widx = 2 * 977 * (int)threadIdx.x + 1;   // odd 32-bit words, spread across array
    int z = (w[widx] == 0) ? 1 : 0;
    atomicAdd(&cnt, z);
    __syncthreads();
    if (threadIdx.x == 0) g_is64 = (cnt > 128) ? 1 : 0;
}

// ---------------- kernel 1: zero accumulators ----------------
__global__ void init_kernel() {
    int i = blockIdx.x * blockDim.x + threadIdx.x;
    if (i < BMAX * DIM) g_pooled[i] = 0.f;
    if (i < BMAX) g_segsum[i] = 0.f;
}

// ---------------- kernel 2: FUSED scores + softmax-weights + pooling ----------------
// Persistent: block owns a CONTIGUOUS range of 64-node tiles. Per tile:
//   1. cp.async x-tile -> smem (double buffered), batch ids -> ssh
//   2. mma: A = W in registers (warp (jg,kh): j-tile jg of 16, k-half kh of 128),
//      B = 8-node groups from smem. acc = partial logits [16j x 8n] per node-group.
//   3. epilogue: combine k-halves (pre-tanh, via lbuf), tanh, ctx-dot, reduce over
//      j (shfl over g, then jbuf over jg), e = exp(score) -> esh (max-free softmax:
//      |score| <= sum|ctx| ~ 5).
//   4. pool from the SAME smem tile: thread d accumulates sum(e_i * x[i][d]);
//      flush to g_pooled/g_segsum only at segment boundaries (batch sorted).
__global__ void __launch_bounds__(256) fused_kernel(
        const float* __restrict__ x,
        const void*  __restrict__ batch,
        const float* __restrict__ W_att,
        const float* __restrict__ b_att,
        const float* __restrict__ ctx,
        int n, int tilesPerBlock, int nTilesTotal) {
    extern __shared__ float xs[];                  // 2 * XBUF floats
    __shared__ float lbuf[4][16][65];              // kh=1 partial logits [jg][j][node]
    __shared__ float jbuf[4][TILE];                // per-jg score partials [jg][node]
    __shared__ float esh[TILE];
    __shared__ int   ssh[2][TILE];

    const int tid  = threadIdx.x;
    const int lane = tid & 31;
    const int wid  = tid >> 5;
    const int g    = lane >> 2;     // 0..7
    const int q    = lane & 3;      // 0..3
    const int jg   = wid & 3;       // j-tile (16 j's)
    const int kh   = wid >> 2;      // k-half (128 k's)
    const int is64 = g_is64;

    int t0 = blockIdx.x * tilesPerBlock;
    int t1 = t0 + tilesPerBlock; if (t1 > nTilesTotal) t1 = nTilesTotal;
    if (t0 >= t1) return;

    // W A-fragments in registers: aw[tu], tu=(ssL*2+sub), k = kh*128+16*ssL+4q+2*sub+{0,1}
    // rows j0 = jg*16+g, j1 = j0+8 (same interleaved-k scheme as proven R2 kernel).
    const int j0 = jg * 16 + g, j1 = j0 + 8;
    float aw[16][4];
    #pragma unroll
    for (int ssL = 0; ssL < 8; ssL++)
        #pragma unroll
        for (int sub = 0; sub < 2; sub++) {
            int k  = kh * 128 + 16 * ssL + 4 * q + 2 * sub;
            int tu = ssL * 2 + sub;
            aw[tu][0] = __uint_as_float(f2tf32(W_att[j0 * DIM + k]));
            aw[tu][1] = __uint_as_float(f2tf32(W_att[j1 * DIM + k]));
            aw[tu][2] = __uint_as_float(f2tf32(W_att[j0 * DIM + k + 1]));
            aw[tu][3] = __uint_as_float(f2tf32(W_att[j1 * DIM + k + 1]));
        }
    const float ctx0 = ctx[j0], ctx1 = ctx[j1];
    const float bb0  = b_att[j0], bb1 = b_att[j1];

    const uint32_t xs_u = (uint32_t)__cvta_generic_to_shared(xs);

    auto load_tile = [&](int t, int buf) {
        int base = t * TILE;
        uint32_t dstb = xs_u + (uint32_t)(buf * XBUF * 4);
        #pragma unroll
        for (int kk = 0; kk < 16; kk++) {
            int idx = tid + 256 * kk;
            int r   = idx >> 6;
            int c   = (idx & 63) << 2;
            int row = base + r; if (row >= n) row = n - 1;
            cp_async16(dstb + (uint32_t)((r * XSTR + c) * 4),
                       x + (size_t)row * DIM + c);
        }
        if (tid < TILE) {
            int row = base + tid; if (row >= n) row = n - 1;
            int s = is64 ? (int)((const long long*)batch)[row]
                         : ((const int*)batch)[row];
            ssh[buf][tid] = s;
        }
        CP_COMMIT();
    };

    load_tile(t0, 0);

    float pacc = 0.f, wacc = 0.f;
    int   cur  = -1;
    const int d = tid;

    for (int t = t0; t < t1; t++) {
        int buf = (t - t0) & 1;
        CP_WAIT0();
        __syncthreads();
        if (t + 1 < t1) load_tile(t + 1, buf ^ 1);

        // ---- mma: all 8 warps; acc[nt] = partial logits for node-group nt ----
        const float* xb = xs + buf * XBUF;
        float acc[8][4];
        #pragma unroll
        for (int nt = 0; nt < 8; nt++) {
            acc[nt][0] = 0.f; acc[nt][1] = 0.f; acc[nt][2] = 0.f; acc[nt][3] = 0.f;
        }
        #pragma unroll
        for (int tu = 0; tu < 16; tu++) {
            int kf = kh * 128 + ((tu >> 1) << 4) + (q << 2) + ((tu & 1) << 1);
            uint32_t a0 = __float_as_uint(aw[tu][0]);
            uint32_t a1 = __float_as_uint(aw[tu][1]);
            uint32_t a2 = __float_as_uint(aw[tu][2]);
            uint32_t a3 = __float_as_uint(aw[tu][3]);
            #pragma unroll
            for (int nt = 0; nt < 8; nt++) {
                float2 b = *(const float2*)(xb + (nt * 8 + g) * XSTR + kf);
                mma_tf32(acc[nt], a0, a1, a2, a3,
                         __float_as_uint(b.x), __float_as_uint(b.y));
            }
        }

        // ---- epilogue: combine k-halves pre-tanh, tanh+ctx, reduce over j ----
        if (kh == 1) {
            #pragma unroll
            for (int nt = 0; nt < 8; nt++) {
                lbuf[jg][g    ][nt * 8 + 2 * q    ] = acc[nt][0];
                lbuf[jg][g    ][nt * 8 + 2 * q + 1] = acc[nt][1];
                lbuf[jg][g + 8][nt * 8 + 2 * q    ] = acc[nt][2];
                lbuf[jg][g + 8][nt * 8 + 2 * q + 1] = acc[nt][3];
            }
        }
        __syncthreads();
        if (kh == 0) {
            #pragma unroll
            for (int nt = 0; nt < 8; nt++) {
                float l0 = acc[nt][0] + lbuf[jg][g    ][nt * 8 + 2 * q    ];
                float l1 = acc[nt][1] + lbuf[jg][g    ][nt * 8 + 2 * q + 1];
                float l2 = acc[nt][2] + lbuf[jg][g + 8][nt * 8 + 2 * q    ];
                float l3 = acc[nt][3] + lbuf[jg][g + 8][nt * 8 + 2 * q + 1];
                float v0 = ctx0 * tanh_apx(l0 + bb0) + ctx1 * tanh_apx(l2 + bb1);
                float v1 = ctx0 * tanh_apx(l1 + bb0) + ctx1 * tanh_apx(l3 + bb1);
                v0 += __shfl_xor_sync(0xffffffffu, v0, 4);
                v0 += __shfl_xor_sync(0xffffffffu, v0, 8);
                v0 += __shfl_xor_sync(0xffffffffu, v0, 16);
                v1 += __shfl_xor_sync(0xffffffffu, v1, 4);
                v1 += __shfl_xor_sync(0xffffffffu, v1, 8);
                v1 += __shfl_xor_sync(0xffffffffu, v1, 16);
                if (g == 0) {
                    jbuf[jg][nt * 8 + 2 * q    ] = v0;
                    jbuf[jg][nt * 8 + 2 * q + 1] = v1;
                }
            }
        }
        __syncthreads();
        if (tid < TILE) {
            int node = t * TILE + tid;
            float sum = jbuf[0][tid] + jbuf[1][tid] + jbuf[2][tid] + jbuf[3][tid];
            esh[tid] = (node < n) ? __expf(sum) : 0.f;
        }
        __syncthreads();

        // ---- pool from the same smem tile ----
        #pragma unroll 4
        for (int i = 0; i < TILE; i++) {
            int s = ssh[buf][i];
            if (s != cur) {                       // uniform across block; rare
                if (cur >= 0) {
                    atomicAdd(&g_pooled[cur * DIM + d], pacc);
                    if (d == 0) atomicAdd(&g_segsum[cur], wacc);
                }
                pacc = 0.f; wacc = 0.f; cur = s;
            }
            float e = esh[i];
            pacc = fmaf(xb[i * XSTR + d], e, pacc);
            if (d == 0) wacc += e;
        }
    }
    if (cur >= 0) {
        atomicAdd(&g_pooled[cur * DIM + d], pacc);
        if (d == 0) atomicAdd(&g_segsum[cur], wacc);
    }
}

// ---------------- kernel 3: output GEMM (normalization folded in) ----------------
__global__ void __launch_bounds__(256) out_kernel(
        const float* __restrict__ W_out, const float* __restrict__ b_out,
        float* __restrict__ out, int Bn) {
    __shared__ float sp[8 * DIM];
    __shared__ float sinv[8];
    int g0 = blockIdx.x * 8;
    for (int i = threadIdx.x; i < 8 * DIM; i += 256) {
        int gg = g0 + (i >> 8);
        sp[i] = (gg < Bn) ? g_pooled[gg * DIM + (i & 255)] : 0.f;
    }
    if (threadIdx.x < 8) {
        int gg = g0 + threadIdx.x;
        float ss = (gg < Bn) ? g_segsum[gg] : 0.f;
        sinv[threadIdx.x] = (ss > 0.f) ? (1.f / ss) : 0.f;
    }
    __syncthreads();
    int d = threadIdx.x;
    float acc[8];
    #pragma unroll
    for (int g = 0; g < 8; g++) acc[g] = 0.f;
    const float4* w4 = (const float4*)(W_out + (size_t)d * DIM);
    #pragma unroll 8
    for (int k4 = 0; k4 < DIM / 4; k4++) {
        float4 w = w4[k4];
        #pragma unroll
        for (int g = 0; g < 8; g++) {
            float4 p = *(const float4*)&sp[g * DIM + 4 * k4];
            acc[g] += w.x * p.x + w.y * p.y + w.z * p.z + w.w * p.w;
        }
    }
    float bb = b_out[d];
    #pragma unroll
    for (int g = 0; g < 8; g++)
        if (g0 + g < Bn) out[(size_t)(g0 + g) * DIM + d] = acc[g] * sinv[g] + bb;
}

// ---------------- launch ----------------
extern "C" void kernel_launch(void* const* d_in, const int* in_sizes, int n_in,
                              void* d_out, int out_size) {
    const float* x     = (const float*)d_in[0];
    const void*  batch = d_in[1];
    const float* W_att = (const float*)d_in[2];
    const float* b_att = (const float*)d_in[3];
    const float* ctx   = (const float*)d_in[4];
    const float* W_out = (const float*)d_in[5];
    const float* b_out = (const float*)d_in[6];
    float* out = (float*)d_out;

    int n  = in_sizes[0] / DIM;       // 500000
    int Bn = out_size / DIM;          // 512
    int nTiles = (n + TILE - 1) / TILE;
    int tilesPerBlock = (nTiles + GRID - 1) / GRID;
    int smemBytes = 2 * XBUF * 4;     // 139264

    cudaFuncSetAttribute(fused_kernel, cudaFuncAttributeMaxDynamicSharedMemorySize, smemBytes);

    detect_kernel<<<1, 256>>>(batch);
    init_kernel<<<(BMAX * DIM + 255) / 256, 256>>>();
    fused_kernel<<<GRID, 256, smemBytes>>>(x, batch, W_att, b_att, ctx,
                                           n, tilesPerBlock, nTiles);
    out_kernel<<<(Bn + 7) / 8, 256>>>(W_out, b_out, out, Bn);
}